// round 6
// baseline (speedup 1.0000x reference)
#include <cuda_runtime.h>
#include <cuda_fp16.h>
#include <cstdint>
#include <math.h>
#include <mma.h>

using namespace nvcuda;

#define DIM 128

// ---------------- scratch (device globals; no allocation allowed) ----------------
__device__ int    g_deg [600000];
__device__ float  g_norm[600000];
__device__ int    g_base  [300000];   // CSR row starts: [dd | gd | dg | gg] (by dst)
__device__ int    g_cursor[300000];
__device__ int    g_bsum  [512];
__device__ int    g_ebuf  [2400000];  // binned src indices
__device__ __half g_hD[100000ull * 256];  // drug proj: cols 0-127 = dd, 128-255 = dg
__device__ __half g_hG[ 50000ull * 256];  // gene proj: cols 0-127 = gd, 128-255 = gg

// ---------------- zero deg ----------------
__global__ void zero_deg() {
    int i = blockIdx.x * blockDim.x + threadIdx.x;
    if (i < 600000 / 4) ((int4*)g_deg)[i] = make_int4(0, 0, 0, 0);
}

// ---------------- degree counting (all 4 etypes) ----------------
__global__ void deg_all(const int* __restrict__ s0, const int* __restrict__ d0, int o0s, int o0d,
                        const int* __restrict__ s1, const int* __restrict__ d1, int o1s, int o1d,
                        const int* __restrict__ s2, const int* __restrict__ d2, int o2s, int o2d,
                        const int* __restrict__ s3, const int* __restrict__ d3, int o3s, int o3d,
                        int E) {
    int i = blockIdx.x * blockDim.x + threadIdx.x;
    const int *s, *d; int os, od, j;
    if (i < E)          { s = s0; d = d0; os = o0s; od = o0d; j = i; }
    else if (i < 2 * E) { s = s1; d = d1; os = o1s; od = o1d; j = i - E; }
    else if (i < 3 * E) { s = s2; d = d2; os = o2s; od = o2d; j = i - 2 * E; }
    else if (i < 4 * E) { s = s3; d = d3; os = o3s; od = o3d; j = i - 3 * E; }
    else return;
    atomicAdd(&g_deg[os + __ldg(s + j)], 1);
    atomicAdd(&g_deg[od + __ldg(d + j)], 1);
}

__global__ void norm_kernel(int n) {
    int i = blockIdx.x * blockDim.x + threadIdx.x;
    if (i < n) g_norm[i] = rsqrtf(fmaxf((float)g_deg[i], 1.0f));
}

// ---------------- 3-phase exclusive scan over concatenated dst degrees ----------------
#define SCAN_BLK 1024
__global__ void scan1(int total, int nDrug, int nGene,
                      int o_dd_d, int o_gd_d, int o_dg_d, int o_gg_d) {
    __shared__ int sh[256];
    const int tid = threadIdx.x;
    const int base = blockIdx.x * SCAN_BLK + tid * 4;
    const int c1 = nDrug, c2 = 2 * nDrug, c3 = 2 * nDrug + nGene;
    int v[4], ssum = 0;
    #pragma unroll
    for (int q = 0; q < 4; q++) {
        int i = base + q, d = 0;
        if (i < total) {
            int idx;
            if (i < c1)      idx = o_dd_d + i;
            else if (i < c2) idx = o_gd_d + i - c1;
            else if (i < c3) idx = o_dg_d + i - c2;
            else             idx = o_gg_d + i - c3;
            d = g_deg[idx];
        }
        v[q] = d; ssum += d;
    }
    sh[tid] = ssum; __syncthreads();
    for (int off = 1; off < 256; off <<= 1) {
        int t = (tid >= off) ? sh[tid - off] : 0;
        __syncthreads();
        sh[tid] += t;
        __syncthreads();
    }
    int run = sh[tid] - ssum;
    if (tid == 255) g_bsum[blockIdx.x] = sh[255];
    #pragma unroll
    for (int q = 0; q < 4; q++) {
        int i = base + q;
        if (i < total) g_base[i] = run;
        run += v[q];
    }
}

__global__ void scan2(int n) {
    __shared__ int sh[512];
    int tid = threadIdx.x;
    int v = (tid < n) ? g_bsum[tid] : 0;
    sh[tid] = v; __syncthreads();
    for (int off = 1; off < 512; off <<= 1) {
        int t = (tid >= off) ? sh[tid - off] : 0;
        __syncthreads();
        sh[tid] += t;
        __syncthreads();
    }
    if (tid < n) g_bsum[tid] = sh[tid] - v;
}

__global__ void scan3(int total) {
    int i = blockIdx.x * blockDim.x + threadIdx.x;
    if (i < total) {
        int v = g_base[i] + g_bsum[i / SCAN_BLK];
        g_base[i] = v;
        g_cursor[i] = v;
    }
}

// ---------------- binning: ebuf[pos] = src (CSR by dst); segment order dd, gd, dg, gg ----------------
__global__ void bin_all(const int* __restrict__ s0, const int* __restrict__ d0,
                        const int* __restrict__ s1, const int* __restrict__ d1,
                        const int* __restrict__ s2, const int* __restrict__ d2,
                        const int* __restrict__ s3, const int* __restrict__ d3,
                        int E, int nDrug, int nGene) {
    int i = blockIdx.x * blockDim.x + threadIdx.x;
    const int *s, *d; int off, j;
    if (i < E)          { s = s0; d = d0; off = 0;                 j = i; }
    else if (i < 2 * E) { s = s1; d = d1; off = nDrug;             j = i - E; }
    else if (i < 3 * E) { s = s2; d = d2; off = 2 * nDrug;         j = i - 2 * E; }
    else if (i < 4 * E) { s = s3; d = d3; off = 2 * nDrug + nGene; j = i - 3 * E; }
    else return;
    int dd = __ldg(d + j);
    int pos = atomicAdd(&g_cursor[off + dd], 1);
    g_ebuf[pos] = __ldg(s + j);
}

// ---------------- projection GEMM: h[:, yh*128:+128] = (nsrc_yh ⊙ x) @ W_yh  (tf32, fp16 out) ----------------
#define APAD 132
#define BPAD 132
#define GEMMH_SMEM ((128 * BPAD + 128 * APAD) * 4)   // 135168 B

__global__ void __launch_bounds__(256, 1)
gemm_h(const float* __restrict__ x,
       const float* __restrict__ ns0, const float* __restrict__ ns1,
       const float* __restrict__ W0, const float* __restrict__ W1,
       __half* __restrict__ h, int M) {
    extern __shared__ float sm[];
    float* Bs = sm;                 // [128][BPAD]
    float* As = sm + 128 * BPAD;    // [128][APAD] (A tile, later C scratch)
    const int tid = threadIdx.x, wid = tid >> 5, lane = tid & 31;
    const int yh = blockIdx.y;
    const float* W  = yh ? W1  : W0;
    const float* ns = yh ? ns1 : ns0;

    // Stage W[k][n] tf32-rounded (coalesced over n).
    for (int i = tid; i < 128 * 128; i += 256)
        Bs[(i >> 7) * BPAD + (i & 127)] = wmma::__float_to_tf32(__ldg(W + i));

    // Stage A = norm_src-scaled x rows, tf32-rounded.
    const int rowBase = blockIdx.x * 128;
    for (int i = tid; i < 4096; i += 256) {     // float4 granularity
        int m = i >> 5, kq = i & 31;
        int gr = rowBase + m;
        float4 v = make_float4(0.f, 0.f, 0.f, 0.f);
        if (gr < M) {
            v = __ldg((const float4*)(x + (size_t)gr * DIM) + kq);
            float s = __ldg(ns + gr);
            v.x *= s; v.y *= s; v.z *= s; v.w *= s;
        }
        float* p = &As[m * APAD + kq * 4];
        p[0] = wmma::__float_to_tf32(v.x);
        p[1] = wmma::__float_to_tf32(v.y);
        p[2] = wmma::__float_to_tf32(v.z);
        p[3] = wmma::__float_to_tf32(v.w);
    }
    __syncthreads();

    const int wrow = wid * 16;
    wmma::fragment<wmma::accumulator, 16, 16, 8, float> c[8];
    #pragma unroll
    for (int t = 0; t < 8; t++) wmma::fill_fragment(c[t], 0.0f);

    #pragma unroll
    for (int ks = 0; ks < 16; ks++) {
        wmma::fragment<wmma::matrix_a, 16, 16, 8, wmma::precision::tf32, wmma::row_major> a;
        wmma::load_matrix_sync(a, &As[wrow * APAD + ks * 8], APAD);
        #pragma unroll
        for (int t = 0; t < 8; t++) {
            wmma::fragment<wmma::matrix_b, 16, 16, 8, wmma::precision::tf32, wmma::row_major> b;
            wmma::load_matrix_sync(b, &Bs[(ks * 8) * BPAD + t * 16], BPAD);
            wmma::mma_sync(c[t], a, b, c[t]);
        }
    }
    __syncthreads();

    // Dump C and write fp16 into h[row][yh*128 .. +127].
    float* Cw = As + wrow * APAD;
    #pragma unroll
    for (int t = 0; t < 8; t++)
        wmma::store_matrix_sync(&Cw[t * 16], c[t], APAD, wmma::mem_row_major);
    __syncwarp();

    const int r = lane >> 1, half = lane & 1;
    const int gr = rowBase + wrow + r;
    if (gr < M) {
        const float* crow = &Cw[r * APAD + half * 64];
        __half2* hp = (__half2*)(h + (size_t)gr * 256 + yh * 128 + half * 64);
        #pragma unroll
        for (int q = 0; q < 32; q++)
            hp[q] = __floats2half2_rn(crow[2 * q], crow[2 * q + 1]);
    }
}

// ---------------- final gather: one warp per dst node, fused epilogue ----------------
// out[r] = l2norm(relu( n0 * Σ_{e∈list0} h0[src_e] + n1 * Σ_{e∈list1} h1[src_e] + bias ))
__device__ __forceinline__ void acc_edges(const __half* __restrict__ h, int colOff,
                                          int j, int e, int lane, float4& acc) {
    const uint2* hp = (const uint2*)(h + colOff);   // row s at hp + s*64 + lane
    for (; j + 4 <= e; j += 4) {
        int s0 = __ldg(g_ebuf + j),     s1 = __ldg(g_ebuf + j + 1);
        int s2 = __ldg(g_ebuf + j + 2), s3 = __ldg(g_ebuf + j + 3);
        uint2 u0 = __ldg(hp + (size_t)s0 * 64 + lane);
        uint2 u1 = __ldg(hp + (size_t)s1 * 64 + lane);
        uint2 u2 = __ldg(hp + (size_t)s2 * 64 + lane);
        uint2 u3 = __ldg(hp + (size_t)s3 * 64 + lane);
        #pragma unroll
        for (int q = 0; q < 4; q++) {
            uint2 u = (q == 0) ? u0 : (q == 1) ? u1 : (q == 2) ? u2 : u3;
            float2 a = __half22float2(*(const __half2*)&u.x);
            float2 b = __half22float2(*(const __half2*)&u.y);
            acc.x += a.x; acc.y += a.y; acc.z += b.x; acc.w += b.y;
        }
    }
    for (; j < e; j++) {
        int s = __ldg(g_ebuf + j);
        uint2 u = __ldg(hp + (size_t)s * 64 + lane);
        float2 a = __half22float2(*(const __half2*)&u.x);
        float2 b = __half22float2(*(const __half2*)&u.y);
        acc.x += a.x; acc.y += a.y; acc.z += b.x; acc.w += b.y;
    }
}

__global__ void __launch_bounds__(256)
gather_out(const float* __restrict__ bias, float* __restrict__ out,
           int nDrug, int nGene,
           int o_dd_d, int o_gd_d, int o_dg_d, int o_gg_d) {
    const int gw   = (blockIdx.x * blockDim.x + threadIdx.x) >> 5;
    const int lane = threadIdx.x & 31;
    if (gw >= nDrug + nGene) return;

    const __half *h0, *h1;
    int colOff, b0, b1, d0i, d1i;
    float n0, n1;
    if (gw < nDrug) {
        int r = gw;
        h0 = g_hD; h1 = g_hG; colOff = 0;
        b0 = __ldg(g_base + r);          d0i = __ldg(g_deg + o_dd_d + r); n0 = __ldg(g_norm + o_dd_d + r);
        b1 = __ldg(g_base + nDrug + r);  d1i = __ldg(g_deg + o_gd_d + r); n1 = __ldg(g_norm + o_gd_d + r);
    } else {
        int r = gw - nDrug;
        h0 = g_hD; h1 = g_hG; colOff = 128;
        b0 = __ldg(g_base + 2 * nDrug + r);         d0i = __ldg(g_deg + o_dg_d + r); n0 = __ldg(g_norm + o_dg_d + r);
        b1 = __ldg(g_base + 2 * nDrug + nGene + r); d1i = __ldg(g_deg + o_gg_d + r); n1 = __ldg(g_norm + o_gg_d + r);
    }

    float4 a0 = make_float4(0.f, 0.f, 0.f, 0.f);
    float4 a1 = make_float4(0.f, 0.f, 0.f, 0.f);
    acc_edges(h0, colOff, b0, b0 + d0i, lane, a0);
    acc_edges(h1, colOff, b1, b1 + d1i, lane, a1);

    float4 bb = __ldg((const float4*)bias + lane);
    float4 v;
    v.x = fmaxf(fmaf(n0, a0.x, fmaf(n1, a1.x, bb.x)), 0.f);
    v.y = fmaxf(fmaf(n0, a0.y, fmaf(n1, a1.y, bb.y)), 0.f);
    v.z = fmaxf(fmaf(n0, a0.z, fmaf(n1, a1.z, bb.z)), 0.f);
    v.w = fmaxf(fmaf(n0, a0.w, fmaf(n1, a1.w, bb.w)), 0.f);

    float ss = v.x * v.x + v.y * v.y + v.z * v.z + v.w * v.w;
    #pragma unroll
    for (int off = 16; off > 0; off >>= 1)
        ss += __shfl_xor_sync(0xffffffffu, ss, off);
    float inv = 1.0f / fmaxf(sqrtf(ss), 1e-12f);
    v.x *= inv; v.y *= inv; v.z *= inv; v.w *= inv;

    *((float4*)(out + (size_t)gw * DIM) + lane) = v;
}

// ---------------- launch ----------------
extern "C" void kernel_launch(void* const* d_in, const int* in_sizes, int n_in,
                              void* d_out, int out_size) {
    const float* x_drug = (const float*)d_in[0];
    const float* x_gene = (const float*)d_in[1];
    const float* W_dd   = (const float*)d_in[2];
    const float* W_dg   = (const float*)d_in[3];
    const float* W_gd   = (const float*)d_in[4];
    const float* W_gg   = (const float*)d_in[5];
    const float* h_bias = (const float*)d_in[6];
    const int* src_dd = (const int*)d_in[7];   const int* dst_dd = (const int*)d_in[8];
    const int* src_dg = (const int*)d_in[9];   const int* dst_dg = (const int*)d_in[10];
    const int* src_gd = (const int*)d_in[11];  const int* dst_gd = (const int*)d_in[12];
    const int* src_gg = (const int*)d_in[13];  const int* dst_gg = (const int*)d_in[14];
    float* out = (float*)d_out;

    const int E     = in_sizes[7];
    const int nDrug = in_sizes[0] / DIM;
    const int nGene = in_sizes[1] / DIM;

    const int o_dd_s = 0;
    const int o_dd_d = o_dd_s + nDrug;
    const int o_dg_s = o_dd_d + nDrug;
    const int o_dg_d = o_dg_s + nDrug;
    const int o_gd_s = o_dg_d + nGene;
    const int o_gd_d = o_gd_s + nGene;
    const int o_gg_s = o_gd_d + nDrug;
    const int o_gg_d = o_gg_s + nGene;
    const int nTot   = o_gg_d + nGene;          // 600000
    const int nScan  = 2 * nDrug + 2 * nGene;   // 300000

    float* normP;
    __half *hD, *hG;
    cudaGetSymbolAddress((void**)&normP, g_norm);
    cudaGetSymbolAddress((void**)&hD, g_hD);
    cudaGetSymbolAddress((void**)&hG, g_hG);

    zero_deg<<<(600000 / 4 + 255) / 256, 256>>>();

    const long long totDeg = 4LL * E;
    deg_all<<<(int)((totDeg + 255) / 256), 256>>>(
        src_dd, dst_dd, o_dd_s, o_dd_d,
        src_dg, dst_dg, o_dg_s, o_dg_d,
        src_gd, dst_gd, o_gd_s, o_gd_d,
        src_gg, dst_gg, o_gg_s, o_gg_d, E);

    norm_kernel<<<(nTot + 255) / 256, 256>>>(nTot);

    const int nScanBlk = (nScan + SCAN_BLK - 1) / SCAN_BLK;
    scan1<<<nScanBlk, 256>>>(nScan, nDrug, nGene, o_dd_d, o_gd_d, o_dg_d, o_gg_d);
    scan2<<<1, 512>>>(nScanBlk);
    scan3<<<(nScan + 255) / 256, 256>>>(nScan);

    bin_all<<<(int)((totDeg + 255) / 256), 256>>>(
        src_dd, dst_dd,
        src_gd, dst_gd,
        src_dg, dst_dg,
        src_gg, dst_gg, E, nDrug, nGene);

    // projection GEMMs: h = (nsrc ⊙ x) @ W, fp16 out; grid.y = etype half
    cudaFuncSetAttribute(gemm_h, cudaFuncAttributeMaxDynamicSharedMemorySize, GEMMH_SMEM);
    dim3 gD((nDrug + 127) / 128, 2), gG((nGene + 127) / 128, 2);
    gemm_h<<<gD, 256, GEMMH_SMEM>>>(x_drug, normP + o_dd_s, normP + o_dg_s,
                                    W_dd, W_dg, hD, nDrug);
    gemm_h<<<gG, 256, GEMMH_SMEM>>>(x_gene, normP + o_gd_s, normP + o_gg_s,
                                    W_gd, W_gg, hG, nGene);

    // final gather + epilogue: one warp per dst node
    const long long gwarps = (long long)(nDrug + nGene) * 32;
    gather_out<<<(int)((gwarps + 255) / 256), 256>>>(
        h_bias, out, nDrug, nGene, o_dd_d, o_gd_d, o_dg_d, o_gg_d);
}

// round 7
// speedup vs baseline: 1.1324x; 1.1324x over previous
#include <cuda_runtime.h>
#include <cuda_fp16.h>
#include <cstdint>
#include <math.h>
#include <mma.h>

using namespace nvcuda;

#define DIM 128

// ---------------- scratch (device globals; no allocation allowed) ----------------
__device__ int    g_deg [600000];
__device__ float  g_norm[600000];
__device__ int    g_base  [300000];   // CSR row starts: [dd | gd | dg | gg] (by dst)
__device__ int    g_cursor[300000];
__device__ int    g_bsum  [512];
__device__ int    g_ebuf  [2400000];  // binned src indices
__device__ __half g_hD[100000ull * 256];  // drug proj: cols 0-127 = dd, 128-255 = dg
__device__ __half g_hG[ 50000ull * 256];  // gene proj: cols 0-127 = gd, 128-255 = gg

// ---------------- zero deg ----------------
__global__ void zero_deg() {
    int i = blockIdx.x * blockDim.x + threadIdx.x;
    if (i < 600000 / 4) ((int4*)g_deg)[i] = make_int4(0, 0, 0, 0);
}

// ---------------- degree counting (all 4 etypes) ----------------
__global__ void deg_all(const int* __restrict__ s0, const int* __restrict__ d0, int o0s, int o0d,
                        const int* __restrict__ s1, const int* __restrict__ d1, int o1s, int o1d,
                        const int* __restrict__ s2, const int* __restrict__ d2, int o2s, int o2d,
                        const int* __restrict__ s3, const int* __restrict__ d3, int o3s, int o3d,
                        int E) {
    int i = blockIdx.x * blockDim.x + threadIdx.x;
    const int *s, *d; int os, od, j;
    if (i < E)          { s = s0; d = d0; os = o0s; od = o0d; j = i; }
    else if (i < 2 * E) { s = s1; d = d1; os = o1s; od = o1d; j = i - E; }
    else if (i < 3 * E) { s = s2; d = d2; os = o2s; od = o2d; j = i - 2 * E; }
    else if (i < 4 * E) { s = s3; d = d3; os = o3s; od = o3d; j = i - 3 * E; }
    else return;
    atomicAdd(&g_deg[os + __ldg(s + j)], 1);
    atomicAdd(&g_deg[od + __ldg(d + j)], 1);
}

__global__ void norm_kernel(int n) {
    int i = blockIdx.x * blockDim.x + threadIdx.x;
    if (i < n) g_norm[i] = rsqrtf(fmaxf((float)g_deg[i], 1.0f));
}

// ---------------- 3-phase exclusive scan over concatenated dst degrees ----------------
#define SCAN_BLK 1024
__global__ void scan1(int total, int nDrug, int nGene,
                      int o_dd_d, int o_gd_d, int o_dg_d, int o_gg_d) {
    __shared__ int sh[256];
    const int tid = threadIdx.x;
    const int base = blockIdx.x * SCAN_BLK + tid * 4;
    const int c1 = nDrug, c2 = 2 * nDrug, c3 = 2 * nDrug + nGene;
    int v[4], ssum = 0;
    #pragma unroll
    for (int q = 0; q < 4; q++) {
        int i = base + q, d = 0;
        if (i < total) {
            int idx;
            if (i < c1)      idx = o_dd_d + i;
            else if (i < c2) idx = o_gd_d + i - c1;
            else if (i < c3) idx = o_dg_d + i - c2;
            else             idx = o_gg_d + i - c3;
            d = g_deg[idx];
        }
        v[q] = d; ssum += d;
    }
    sh[tid] = ssum; __syncthreads();
    for (int off = 1; off < 256; off <<= 1) {
        int t = (tid >= off) ? sh[tid - off] : 0;
        __syncthreads();
        sh[tid] += t;
        __syncthreads();
    }
    int run = sh[tid] - ssum;
    if (tid == 255) g_bsum[blockIdx.x] = sh[255];
    #pragma unroll
    for (int q = 0; q < 4; q++) {
        int i = base + q;
        if (i < total) g_base[i] = run;
        run += v[q];
    }
}

__global__ void scan2(int n) {
    __shared__ int sh[512];
    int tid = threadIdx.x;
    int v = (tid < n) ? g_bsum[tid] : 0;
    sh[tid] = v; __syncthreads();
    for (int off = 1; off < 512; off <<= 1) {
        int t = (tid >= off) ? sh[tid - off] : 0;
        __syncthreads();
        sh[tid] += t;
        __syncthreads();
    }
    if (tid < n) g_bsum[tid] = sh[tid] - v;
}

__global__ void scan3(int total) {
    int i = blockIdx.x * blockDim.x + threadIdx.x;
    if (i < total) {
        int v = g_base[i] + g_bsum[i / SCAN_BLK];
        g_base[i] = v;
        g_cursor[i] = v;
    }
}

// ---------------- binning: ebuf[pos] = src (CSR by dst); segment order dd, gd, dg, gg ----------------
__global__ void bin_all(const int* __restrict__ s0, const int* __restrict__ d0,
                        const int* __restrict__ s1, const int* __restrict__ d1,
                        const int* __restrict__ s2, const int* __restrict__ d2,
                        const int* __restrict__ s3, const int* __restrict__ d3,
                        int E, int nDrug, int nGene) {
    int i = blockIdx.x * blockDim.x + threadIdx.x;
    const int *s, *d; int off, j;
    if (i < E)          { s = s0; d = d0; off = 0;                 j = i; }
    else if (i < 2 * E) { s = s1; d = d1; off = nDrug;             j = i - E; }
    else if (i < 3 * E) { s = s2; d = d2; off = 2 * nDrug;         j = i - 2 * E; }
    else if (i < 4 * E) { s = s3; d = d3; off = 2 * nDrug + nGene; j = i - 3 * E; }
    else return;
    int dd = __ldg(d + j);
    int pos = atomicAdd(&g_cursor[off + dd], 1);
    g_ebuf[pos] = __ldg(s + j);
}

// ---------------- projection GEMM: h[:, yh*128:+128] = (nsrc_yh ⊙ x) @ W_yh  (tf32, fp16 out) ----------------
#define APAD 132
#define BPAD 132
#define GEMMH_SMEM ((128 * BPAD + 128 * APAD) * 4)   // 135168 B

__global__ void __launch_bounds__(256, 1)
gemm_h(const float* __restrict__ x,
       const float* __restrict__ ns0, const float* __restrict__ ns1,
       const float* __restrict__ W0, const float* __restrict__ W1,
       __half* __restrict__ h, int M) {
    extern __shared__ float sm[];
    float* Bs = sm;                 // [128][BPAD]
    float* As = sm + 128 * BPAD;    // [128][APAD] (A tile, later C scratch)
    const int tid = threadIdx.x, wid = tid >> 5;
    const int yh = blockIdx.y;
    const float* W  = yh ? W1  : W0;
    const float* ns = yh ? ns1 : ns0;

    // Stage W[k][n] tf32-rounded (coalesced over n).
    for (int i = tid; i < 128 * 128; i += 256)
        Bs[(i >> 7) * BPAD + (i & 127)] = wmma::__float_to_tf32(__ldg(W + i));

    // Stage A = norm_src-scaled x rows, tf32-rounded.
    const int rowBase = blockIdx.x * 128;
    for (int i = tid; i < 4096; i += 256) {     // float4 granularity
        int m = i >> 5, kq = i & 31;
        int gr = rowBase + m;
        float4 v = make_float4(0.f, 0.f, 0.f, 0.f);
        if (gr < M) {
            v = __ldg((const float4*)(x + (size_t)gr * DIM) + kq);
            float s = __ldg(ns + gr);
            v.x *= s; v.y *= s; v.z *= s; v.w *= s;
        }
        float* p = &As[m * APAD + kq * 4];
        p[0] = wmma::__float_to_tf32(v.x);
        p[1] = wmma::__float_to_tf32(v.y);
        p[2] = wmma::__float_to_tf32(v.z);
        p[3] = wmma::__float_to_tf32(v.w);
    }
    __syncthreads();

    const int wrow = wid * 16;
    wmma::fragment<wmma::accumulator, 16, 16, 8, float> c[8];
    #pragma unroll
    for (int t = 0; t < 8; t++) wmma::fill_fragment(c[t], 0.0f);

    #pragma unroll
    for (int ks = 0; ks < 16; ks++) {
        wmma::fragment<wmma::matrix_a, 16, 16, 8, wmma::precision::tf32, wmma::row_major> a;
        wmma::load_matrix_sync(a, &As[wrow * APAD + ks * 8], APAD);
        #pragma unroll
        for (int t = 0; t < 8; t++) {
            wmma::fragment<wmma::matrix_b, 16, 16, 8, wmma::precision::tf32, wmma::row_major> b;
            wmma::load_matrix_sync(b, &Bs[(ks * 8) * BPAD + t * 16], BPAD);
            wmma::mma_sync(c[t], a, b, c[t]);
        }
    }
    __syncthreads();

    // Dump C tiles to smem (As region is free now).
    float* Cw = As + wrow * APAD;
    #pragma unroll
    for (int t = 0; t < 8; t++)
        wmma::store_matrix_sync(&Cw[t * 16], c[t], APAD, wmma::mem_row_major);
    __syncthreads();

    // Coalesced fp16 write: consecutive threads -> consecutive half2 columns.
    for (int i = tid; i < 128 * 64; i += 256) {
        int m = i >> 6, c2 = i & 63;
        int gr = rowBase + m;
        if (gr < M) {
            const float* p = &As[m * APAD + c2 * 2];
            __half2* hp = (__half2*)(h + (size_t)gr * 256 + yh * 128);
            hp[c2] = __floats2half2_rn(p[0], p[1]);
        }
    }
}

// ---------------- final gather: TWO warps per dst node (one per etype list) ----------------
// out[r] = l2norm(relu( n0 * Σ h0[src] + n1 * Σ h1[src] + bias ))
__global__ void __launch_bounds__(256)
gather_out(const float* __restrict__ bias, float* __restrict__ out,
           int nDrug, int nGene,
           int o_dd_d, int o_gd_d, int o_dg_d, int o_gg_d) {
    __shared__ float4 red[8][32];
    const int tid  = threadIdx.x;
    const int wid  = tid >> 5, lane = tid & 31;
    const int node = blockIdx.x * 4 + (wid >> 1);   // 4 dst nodes per block
    const int list = wid & 1;
    const int nNodes = nDrug + nGene;

    float4 acc = make_float4(0.f, 0.f, 0.f, 0.f);
    float nn = 0.f;

    if (node < nNodes) {
        const __half* h; int colOff, b, dg, odst;
        if (node < nDrug) {
            int r = node; colOff = 0;
            if (list == 0) { h = g_hD; b = __ldg(g_base + r);         odst = o_dd_d; }
            else           { h = g_hG; b = __ldg(g_base + nDrug + r); odst = o_gd_d; }
            dg = __ldg(g_deg + odst + r); nn = __ldg(g_norm + odst + r);
        } else {
            int r = node - nDrug; colOff = 128;
            if (list == 0) { h = g_hD; b = __ldg(g_base + 2 * nDrug + r);         odst = o_dg_d; }
            else           { h = g_hG; b = __ldg(g_base + 2 * nDrug + nGene + r); odst = o_gg_d; }
            dg = __ldg(g_deg + odst + r); nn = __ldg(g_norm + odst + r);
        }

        const uint2* hp = (const uint2*)(h + colOff);   // row s at hp + s*64 + lane
        int j = b; const int e = b + dg;
        for (; j + 8 <= e; j += 8) {
            int s[8];
            #pragma unroll
            for (int q = 0; q < 8; q++) s[q] = __ldg(g_ebuf + j + q);
            uint2 u[8];
            #pragma unroll
            for (int q = 0; q < 8; q++) u[q] = __ldg(hp + (size_t)s[q] * 64 + lane);
            #pragma unroll
            for (int q = 0; q < 8; q++) {
                float2 a = __half22float2(*(const __half2*)&u[q].x);
                float2 c = __half22float2(*(const __half2*)&u[q].y);
                acc.x += a.x; acc.y += a.y; acc.z += c.x; acc.w += c.y;
            }
        }
        for (; j + 2 <= e; j += 2) {
            int s0 = __ldg(g_ebuf + j), s1 = __ldg(g_ebuf + j + 1);
            uint2 u0 = __ldg(hp + (size_t)s0 * 64 + lane);
            uint2 u1 = __ldg(hp + (size_t)s1 * 64 + lane);
            float2 a0 = __half22float2(*(const __half2*)&u0.x);
            float2 c0 = __half22float2(*(const __half2*)&u0.y);
            float2 a1 = __half22float2(*(const __half2*)&u1.x);
            float2 c1 = __half22float2(*(const __half2*)&u1.y);
            acc.x += a0.x + a1.x; acc.y += a0.y + a1.y;
            acc.z += c0.x + c1.x; acc.w += c0.y + c1.y;
        }
        if (j < e) {
            int s = __ldg(g_ebuf + j);
            uint2 u = __ldg(hp + (size_t)s * 64 + lane);
            float2 a = __half22float2(*(const __half2*)&u.x);
            float2 c = __half22float2(*(const __half2*)&u.y);
            acc.x += a.x; acc.y += a.y; acc.z += c.x; acc.w += c.y;
        }
    }
    acc.x *= nn; acc.y *= nn; acc.z *= nn; acc.w *= nn;
    red[wid][lane] = acc;
    __syncthreads();

    if (list == 0 && node < nNodes) {
        float4 o = red[wid + 1][lane];
        float4 bb = __ldg((const float4*)bias + lane);
        float4 v;
        v.x = fmaxf(acc.x + o.x + bb.x, 0.f);
        v.y = fmaxf(acc.y + o.y + bb.y, 0.f);
        v.z = fmaxf(acc.z + o.z + bb.z, 0.f);
        v.w = fmaxf(acc.w + o.w + bb.w, 0.f);

        float ss = v.x * v.x + v.y * v.y + v.z * v.z + v.w * v.w;
        #pragma unroll
        for (int off = 16; off > 0; off >>= 1)
            ss += __shfl_xor_sync(0xffffffffu, ss, off);
        float inv = 1.0f / fmaxf(sqrtf(ss), 1e-12f);
        v.x *= inv; v.y *= inv; v.z *= inv; v.w *= inv;

        *((float4*)(out + (size_t)node * DIM) + lane) = v;
    }
}

// ---------------- launch ----------------
extern "C" void kernel_launch(void* const* d_in, const int* in_sizes, int n_in,
                              void* d_out, int out_size) {
    const float* x_drug = (const float*)d_in[0];
    const float* x_gene = (const float*)d_in[1];
    const float* W_dd   = (const float*)d_in[2];
    const float* W_dg   = (const float*)d_in[3];
    const float* W_gd   = (const float*)d_in[4];
    const float* W_gg   = (const float*)d_in[5];
    const float* h_bias = (const float*)d_in[6];
    const int* src_dd = (const int*)d_in[7];   const int* dst_dd = (const int*)d_in[8];
    const int* src_dg = (const int*)d_in[9];   const int* dst_dg = (const int*)d_in[10];
    const int* src_gd = (const int*)d_in[11];  const int* dst_gd = (const int*)d_in[12];
    const int* src_gg = (const int*)d_in[13];  const int* dst_gg = (const int*)d_in[14];
    float* out = (float*)d_out;

    const int E     = in_sizes[7];
    const int nDrug = in_sizes[0] / DIM;
    const int nGene = in_sizes[1] / DIM;

    const int o_dd_s = 0;
    const int o_dd_d = o_dd_s + nDrug;
    const int o_dg_s = o_dd_d + nDrug;
    const int o_dg_d = o_dg_s + nDrug;
    const int o_gd_s = o_dg_d + nGene;
    const int o_gd_d = o_gd_s + nGene;
    const int o_gg_s = o_gd_d + nDrug;
    const int o_gg_d = o_gg_s + nGene;
    const int nTot   = o_gg_d + nGene;          // 600000
    const int nScan  = 2 * nDrug + 2 * nGene;   // 300000

    float* normP;
    __half *hD, *hG;
    cudaGetSymbolAddress((void**)&normP, g_norm);
    cudaGetSymbolAddress((void**)&hD, g_hD);
    cudaGetSymbolAddress((void**)&hG, g_hG);

    zero_deg<<<(600000 / 4 + 255) / 256, 256>>>();

    const long long totDeg = 4LL * E;
    deg_all<<<(int)((totDeg + 255) / 256), 256>>>(
        src_dd, dst_dd, o_dd_s, o_dd_d,
        src_dg, dst_dg, o_dg_s, o_dg_d,
        src_gd, dst_gd, o_gd_s, o_gd_d,
        src_gg, dst_gg, o_gg_s, o_gg_d, E);

    norm_kernel<<<(nTot + 255) / 256, 256>>>(nTot);

    const int nScanBlk = (nScan + SCAN_BLK - 1) / SCAN_BLK;
    scan1<<<nScanBlk, 256>>>(nScan, nDrug, nGene, o_dd_d, o_gd_d, o_dg_d, o_gg_d);
    scan2<<<1, 512>>>(nScanBlk);
    scan3<<<(nScan + 255) / 256, 256>>>(nScan);

    bin_all<<<(int)((totDeg + 255) / 256), 256>>>(
        src_dd, dst_dd,
        src_gd, dst_gd,
        src_dg, dst_dg,
        src_gg, dst_gg, E, nDrug, nGene);

    // projection GEMMs: h = (nsrc ⊙ x) @ W, fp16 out; grid.y = etype half
    cudaFuncSetAttribute(gemm_h, cudaFuncAttributeMaxDynamicSharedMemorySize, GEMMH_SMEM);
    dim3 gD((nDrug + 127) / 128, 2), gG((nGene + 127) / 128, 2);
    gemm_h<<<gD, 256, GEMMH_SMEM>>>(x_drug, normP + o_dd_s, normP + o_dg_s,
                                    W_dd, W_dg, hD, nDrug);
    gemm_h<<<gG, 256, GEMMH_SMEM>>>(x_gene, normP + o_gd_s, normP + o_gg_s,
                                    W_gd, W_gg, hG, nGene);

    // final gather + epilogue: two warps per dst node, 4 nodes per block
    gather_out<<<(nDrug + nGene + 3) / 4, 256>>>(
        h_bias, out, nDrug, nGene, o_dd_d, o_gd_d, o_dg_d, o_gg_d);
}

// round 8
// speedup vs baseline: 1.7339x; 1.5311x over previous
#include <cuda_runtime.h>
#include <cuda_fp16.h>
#include <cstdint>
#include <math.h>
#include <mma.h>

using namespace nvcuda;

#define DIM 128

// ---------------- scratch (device globals; no allocation allowed) ----------------
__device__ int    g_deg [600000];
__device__ float  g_norm[600000];
__device__ int    g_base  [300000];   // CSR row starts: [dd | gd | dg | gg] (by dst)
__device__ int    g_cursor[300000];
__device__ int    g_bsum  [512];
__device__ int    g_ebuf  [2400000];  // binned src indices
__device__ __half g_hD[100000ull * 256];  // drug proj: cols 0-127 = dd, 128-255 = dg
__device__ __half g_hG[ 50000ull * 256];  // gene proj: cols 0-127 = gd, 128-255 = gg

// ---------------- zero deg ----------------
__global__ void zero_deg() {
    int i = blockIdx.x * blockDim.x + threadIdx.x;
    if (i < 600000 / 4) ((int4*)g_deg)[i] = make_int4(0, 0, 0, 0);
}

// ---------------- degree counting (all 4 etypes) ----------------
__global__ void deg_all(const int* __restrict__ s0, const int* __restrict__ d0, int o0s, int o0d,
                        const int* __restrict__ s1, const int* __restrict__ d1, int o1s, int o1d,
                        const int* __restrict__ s2, const int* __restrict__ d2, int o2s, int o2d,
                        const int* __restrict__ s3, const int* __restrict__ d3, int o3s, int o3d,
                        int E) {
    int i = blockIdx.x * blockDim.x + threadIdx.x;
    const int *s, *d; int os, od, j;
    if (i < E)          { s = s0; d = d0; os = o0s; od = o0d; j = i; }
    else if (i < 2 * E) { s = s1; d = d1; os = o1s; od = o1d; j = i - E; }
    else if (i < 3 * E) { s = s2; d = d2; os = o2s; od = o2d; j = i - 2 * E; }
    else if (i < 4 * E) { s = s3; d = d3; os = o3s; od = o3d; j = i - 3 * E; }
    else return;
    atomicAdd(&g_deg[os + __ldg(s + j)], 1);
    atomicAdd(&g_deg[od + __ldg(d + j)], 1);
}

__global__ void norm_kernel(int n) {
    int i = blockIdx.x * blockDim.x + threadIdx.x;
    if (i < n) g_norm[i] = rsqrtf(fmaxf((float)g_deg[i], 1.0f));
}

// ---------------- 3-phase exclusive scan over concatenated dst degrees ----------------
#define SCAN_BLK 1024
__global__ void scan1(int total, int nDrug, int nGene,
                      int o_dd_d, int o_gd_d, int o_dg_d, int o_gg_d) {
    __shared__ int sh[256];
    const int tid = threadIdx.x;
    const int base = blockIdx.x * SCAN_BLK + tid * 4;
    const int c1 = nDrug, c2 = 2 * nDrug, c3 = 2 * nDrug + nGene;
    int v[4], ssum = 0;
    #pragma unroll
    for (int q = 0; q < 4; q++) {
        int i = base + q, d = 0;
        if (i < total) {
            int idx;
            if (i < c1)      idx = o_dd_d + i;
            else if (i < c2) idx = o_gd_d + i - c1;
            else if (i < c3) idx = o_dg_d + i - c2;
            else             idx = o_gg_d + i - c3;
            d = g_deg[idx];
        }
        v[q] = d; ssum += d;
    }
    sh[tid] = ssum; __syncthreads();
    for (int off = 1; off < 256; off <<= 1) {
        int t = (tid >= off) ? sh[tid - off] : 0;
        __syncthreads();
        sh[tid] += t;
        __syncthreads();
    }
    int run = sh[tid] - ssum;
    if (tid == 255) g_bsum[blockIdx.x] = sh[255];
    #pragma unroll
    for (int q = 0; q < 4; q++) {
        int i = base + q;
        if (i < total) g_base[i] = run;
        run += v[q];
    }
}

__global__ void scan2(int n) {
    __shared__ int sh[512];
    int tid = threadIdx.x;
    int v = (tid < n) ? g_bsum[tid] : 0;
    sh[tid] = v; __syncthreads();
    for (int off = 1; off < 512; off <<= 1) {
        int t = (tid >= off) ? sh[tid - off] : 0;
        __syncthreads();
        sh[tid] += t;
        __syncthreads();
    }
    if (tid < n) g_bsum[tid] = sh[tid] - v;
}

__global__ void scan3(int total) {
    int i = blockIdx.x * blockDim.x + threadIdx.x;
    if (i < total) {
        int v = g_base[i] + g_bsum[i / SCAN_BLK];
        g_base[i] = v;
        g_cursor[i] = v;
    }
}

// ---------------- binning: ebuf[pos] = src (CSR by dst); segment order dd, gd, dg, gg ----------------
__global__ void bin_all(const int* __restrict__ s0, const int* __restrict__ d0,
                        const int* __restrict__ s1, const int* __restrict__ d1,
                        const int* __restrict__ s2, const int* __restrict__ d2,
                        const int* __restrict__ s3, const int* __restrict__ d3,
                        int E, int nDrug, int nGene) {
    int i = blockIdx.x * blockDim.x + threadIdx.x;
    const int *s, *d; int off, j;
    if (i < E)          { s = s0; d = d0; off = 0;                 j = i; }
    else if (i < 2 * E) { s = s1; d = d1; off = nDrug;             j = i - E; }
    else if (i < 3 * E) { s = s2; d = d2; off = 2 * nDrug;         j = i - 2 * E; }
    else if (i < 4 * E) { s = s3; d = d3; off = 2 * nDrug + nGene; j = i - 3 * E; }
    else return;
    int dd = __ldg(d + j);
    int pos = atomicAdd(&g_cursor[off + dd], 1);
    g_ebuf[pos] = __ldg(s + j);
}

// ---------------- projection GEMM (fp16 m16n16k16): h[:, yh*128:+128] = (nsrc ⊙ x) @ W ----------------
// smem: Bs half[128][144] | As half[128][144]  (stage)  overlaid by  Cf float[128][136] (epilogue)
#define HPAD 144
#define CPAD 136
#define GEMMH_SMEM (2 * 128 * HPAD * 2)     // 73728 B  (>= 128*CPAD*4 = 69632)

__global__ void __launch_bounds__(256, 2)
gemm_h(const float* __restrict__ x,
       const float* __restrict__ ns0, const float* __restrict__ ns1,
       const float* __restrict__ W0, const float* __restrict__ W1,
       __half* __restrict__ h, int M) {
    extern __shared__ char smraw[];
    __half* Bs = (__half*)smraw;                  // [128][HPAD]
    __half* As = (__half*)smraw + 128 * HPAD;     // [128][HPAD]
    float*  Cf = (float*)smraw;                   // [128][CPAD] (overlay after MMA)
    const int tid = threadIdx.x, wid = tid >> 5;
    const int yh = blockIdx.y;
    const float* W  = yh ? W1  : W0;
    const float* ns = yh ? ns1 : ns0;

    // Stage W[k][n] -> half (coalesced over n, float4 -> 2x half2).
    for (int i = tid; i < 128 * 32; i += 256) {   // float4 granularity
        int k = i >> 5, nq = i & 31;
        float4 v = __ldg((const float4*)(W + k * 128) + nq);
        __half2* p = (__half2*)&Bs[k * HPAD + nq * 4];
        p[0] = __floats2half2_rn(v.x, v.y);
        p[1] = __floats2half2_rn(v.z, v.w);
    }

    // Stage A = norm_src-scaled x rows -> half.
    const int rowBase = blockIdx.x * 128;
    for (int i = tid; i < 4096; i += 256) {
        int m = i >> 5, kq = i & 31;
        int gr = rowBase + m;
        float4 v = make_float4(0.f, 0.f, 0.f, 0.f);
        if (gr < M) {
            v = __ldg((const float4*)(x + (size_t)gr * DIM) + kq);
            float s = __ldg(ns + gr);
            v.x *= s; v.y *= s; v.z *= s; v.w *= s;
        }
        __half2* p = (__half2*)&As[m * HPAD + kq * 4];
        p[0] = __floats2half2_rn(v.x, v.y);
        p[1] = __floats2half2_rn(v.z, v.w);
    }
    __syncthreads();

    const int wrow = wid * 16;
    wmma::fragment<wmma::accumulator, 16, 16, 16, float> c[8];
    #pragma unroll
    for (int t = 0; t < 8; t++) wmma::fill_fragment(c[t], 0.0f);

    #pragma unroll
    for (int ks = 0; ks < 8; ks++) {
        wmma::fragment<wmma::matrix_a, 16, 16, 16, __half, wmma::row_major> a;
        wmma::load_matrix_sync(a, &As[wrow * HPAD + ks * 16], HPAD);
        #pragma unroll
        for (int t = 0; t < 8; t++) {
            wmma::fragment<wmma::matrix_b, 16, 16, 16, __half, wmma::row_major> b;
            wmma::load_matrix_sync(b, &Bs[(ks * 16) * HPAD + t * 16], HPAD);
            wmma::mma_sync(c[t], a, b, c[t]);
        }
    }
    __syncthreads();   // stage fully consumed -> safe to overlay C

    float* Cw = Cf + wrow * CPAD;
    #pragma unroll
    for (int t = 0; t < 8; t++)
        wmma::store_matrix_sync(&Cw[t * 16], c[t], CPAD, wmma::mem_row_major);
    __syncthreads();

    // Coalesced fp16 write: consecutive threads -> consecutive half2 columns.
    for (int i = tid; i < 128 * 64; i += 256) {
        int m = i >> 6, c2 = i & 63;
        int gr = rowBase + m;
        if (gr < M) {
            const float* p = &Cf[m * CPAD + c2 * 2];
            __half2* hp = (__half2*)(h + (size_t)gr * 256 + yh * 128);
            hp[c2] = __floats2half2_rn(p[0], p[1]);
        }
    }
}

// ---------------- final gather: TWO warps per dst node (one per etype list) ----------------
__global__ void __launch_bounds__(256)
gather_out(const float* __restrict__ bias, float* __restrict__ out,
           int nDrug, int nGene,
           int o_dd_d, int o_gd_d, int o_dg_d, int o_gg_d) {
    __shared__ float4 red[8][32];
    const int tid  = threadIdx.x;
    const int wid  = tid >> 5, lane = tid & 31;
    const int node = blockIdx.x * 4 + (wid >> 1);
    const int list = wid & 1;
    const int nNodes = nDrug + nGene;

    float4 acc = make_float4(0.f, 0.f, 0.f, 0.f);
    float nn = 0.f;

    if (node < nNodes) {
        const __half* h; int colOff, b, dg, odst;
        if (node < nDrug) {
            int r = node; colOff = 0;
            if (list == 0) { h = g_hD; b = __ldg(g_base + r);         odst = o_dd_d; }
            else           { h = g_hG; b = __ldg(g_base + nDrug + r); odst = o_gd_d; }
            dg = __ldg(g_deg + odst + r); nn = __ldg(g_norm + odst + r);
        } else {
            int r = node - nDrug; colOff = 128;
            if (list == 0) { h = g_hD; b = __ldg(g_base + 2 * nDrug + r);         odst = o_dg_d; }
            else           { h = g_hG; b = __ldg(g_base + 2 * nDrug + nGene + r); odst = o_gg_d; }
            dg = __ldg(g_deg + odst + r); nn = __ldg(g_norm + odst + r);
        }

        const uint2* hp = (const uint2*)(h + colOff);
        int j = b; const int e = b + dg;
        for (; j + 8 <= e; j += 8) {
            int s[8];
            #pragma unroll
            for (int q = 0; q < 8; q++) s[q] = __ldg(g_ebuf + j + q);
            uint2 u[8];
            #pragma unroll
            for (int q = 0; q < 8; q++) u[q] = __ldg(hp + (size_t)s[q] * 64 + lane);
            #pragma unroll
            for (int q = 0; q < 8; q++) {
                float2 a = __half22float2(*(const __half2*)&u[q].x);
                float2 c = __half22float2(*(const __half2*)&u[q].y);
                acc.x += a.x; acc.y += a.y; acc.z += c.x; acc.w += c.y;
            }
        }
        for (; j + 2 <= e; j += 2) {
            int s0 = __ldg(g_ebuf + j), s1 = __ldg(g_ebuf + j + 1);
            uint2 u0 = __ldg(hp + (size_t)s0 * 64 + lane);
            uint2 u1 = __ldg(hp + (size_t)s1 * 64 + lane);
            float2 a0 = __half22float2(*(const __half2*)&u0.x);
            float2 c0 = __half22float2(*(const __half2*)&u0.y);
            float2 a1 = __half22float2(*(const __half2*)&u1.x);
            float2 c1 = __half22float2(*(const __half2*)&u1.y);
            acc.x += a0.x + a1.x; acc.y += a0.y + a1.y;
            acc.z += c0.x + c1.x; acc.w += c0.y + c1.y;
        }
        if (j < e) {
            int s = __ldg(g_ebuf + j);
            uint2 u = __ldg(hp + (size_t)s * 64 + lane);
            float2 a = __half22float2(*(const __half2*)&u.x);
            float2 c = __half22float2(*(const __half2*)&u.y);
            acc.x += a.x; acc.y += a.y; acc.z += c.x; acc.w += c.y;
        }
    }
    acc.x *= nn; acc.y *= nn; acc.z *= nn; acc.w *= nn;
    red[wid][lane] = acc;
    __syncthreads();

    if (list == 0 && node < nNodes) {
        float4 o = red[wid + 1][lane];
        float4 bb = __ldg((const float4*)bias + lane);
        float4 v;
        v.x = fmaxf(acc.x + o.x + bb.x, 0.f);
        v.y = fmaxf(acc.y + o.y + bb.y, 0.f);
        v.z = fmaxf(acc.z + o.z + bb.z, 0.f);
        v.w = fmaxf(acc.w + o.w + bb.w, 0.f);

        float ss = v.x * v.x + v.y * v.y + v.z * v.z + v.w * v.w;
        #pragma unroll
        for (int off = 16; off > 0; off >>= 1)
            ss += __shfl_xor_sync(0xffffffffu, ss, off);
        float inv = 1.0f / fmaxf(sqrtf(ss), 1e-12f);
        v.x *= inv; v.y *= inv; v.z *= inv; v.w *= inv;

        *((float4*)(out + (size_t)node * DIM) + lane) = v;
    }
}

// ---------------- launch ----------------
extern "C" void kernel_launch(void* const* d_in, const int* in_sizes, int n_in,
                              void* d_out, int out_size) {
    const float* x_drug = (const float*)d_in[0];
    const float* x_gene = (const float*)d_in[1];
    const float* W_dd   = (const float*)d_in[2];
    const float* W_dg   = (const float*)d_in[3];
    const float* W_gd   = (const float*)d_in[4];
    const float* W_gg   = (const float*)d_in[5];
    const float* h_bias = (const float*)d_in[6];
    const int* src_dd = (const int*)d_in[7];   const int* dst_dd = (const int*)d_in[8];
    const int* src_dg = (const int*)d_in[9];   const int* dst_dg = (const int*)d_in[10];
    const int* src_gd = (const int*)d_in[11];  const int* dst_gd = (const int*)d_in[12];
    const int* src_gg = (const int*)d_in[13];  const int* dst_gg = (const int*)d_in[14];
    float* out = (float*)d_out;

    const int E     = in_sizes[7];
    const int nDrug = in_sizes[0] / DIM;
    const int nGene = in_sizes[1] / DIM;

    const int o_dd_s = 0;
    const int o_dd_d = o_dd_s + nDrug;
    const int o_dg_s = o_dd_d + nDrug;
    const int o_dg_d = o_dg_s + nDrug;
    const int o_gd_s = o_dg_d + nGene;
    const int o_gd_d = o_gd_s + nGene;
    const int o_gg_s = o_gd_d + nDrug;
    const int o_gg_d = o_gg_s + nGene;
    const int nTot   = o_gg_d + nGene;          // 600000
    const int nScan  = 2 * nDrug + 2 * nGene;   // 300000

    float* normP;
    __half *hD, *hG;
    cudaGetSymbolAddress((void**)&normP, g_norm);
    cudaGetSymbolAddress((void**)&hD, g_hD);
    cudaGetSymbolAddress((void**)&hG, g_hG);

    zero_deg<<<(600000 / 4 + 255) / 256, 256>>>();

    const long long totDeg = 4LL * E;
    deg_all<<<(int)((totDeg + 255) / 256), 256>>>(
        src_dd, dst_dd, o_dd_s, o_dd_d,
        src_dg, dst_dg, o_dg_s, o_dg_d,
        src_gd, dst_gd, o_gd_s, o_gd_d,
        src_gg, dst_gg, o_gg_s, o_gg_d, E);

    norm_kernel<<<(nTot + 255) / 256, 256>>>(nTot);

    const int nScanBlk = (nScan + SCAN_BLK - 1) / SCAN_BLK;
    scan1<<<nScanBlk, 256>>>(nScan, nDrug, nGene, o_dd_d, o_gd_d, o_dg_d, o_gg_d);
    scan2<<<1, 512>>>(nScanBlk);
    scan3<<<(nScan + 255) / 256, 256>>>(nScan);

    bin_all<<<(int)((totDeg + 255) / 256), 256>>>(
        src_dd, dst_dd,
        src_gd, dst_gd,
        src_dg, dst_dg,
        src_gg, dst_gg, E, nDrug, nGene);

    // projection GEMMs: h = (nsrc ⊙ x) @ W, fp16 in/out, fp32 accum
    cudaFuncSetAttribute(gemm_h, cudaFuncAttributeMaxDynamicSharedMemorySize, GEMMH_SMEM);
    dim3 gD((nDrug + 127) / 128, 2), gG((nGene + 127) / 128, 2);
    gemm_h<<<gD, 256, GEMMH_SMEM>>>(x_drug, normP + o_dd_s, normP + o_dg_s,
                                    W_dd, W_dg, hD, nDrug);
    gemm_h<<<gG, 256, GEMMH_SMEM>>>(x_gene, normP + o_gd_s, normP + o_gg_s,
                                    W_gd, W_gg, hG, nGene);

    // final gather + epilogue: two warps per dst node, 4 nodes per block
    gather_out<<<(nDrug + nGene + 3) / 4, 256>>>(
        h_bias, out, nDrug, nGene, o_dd_d, o_gd_d, o_dg_d, o_gg_d);
}